// round 10
// baseline (speedup 1.0000x reference)
#include <cuda_runtime.h>
#include <cuda_bf16.h>
#include <math.h>
#include <stdint.h>

#define BB 4
#define CC 128
#define NNp 32768
#define KK9 9
#define KS5 5
#define EPSb 1e-5f
#define MTOT 131072.0f
#define PROWS 1024            // 256 n-tiles x 4 batches

// ---------------- scratch ----------------
__device__ __nv_bfloat16 d_pl0[(size_t)BB*NNp*256];   // planes [B,N, hi128|lo128]
__device__ __nv_bfloat16 d_pl1[(size_t)BB*NNp*256];
__device__ float d_bufA[(size_t)BB*NNp*CC];           // gconv raw out [B,N,C]
__device__ float d_bufB[(size_t)BB*NNp*CC];           // wconv raw out [B,N,C]
__device__ float d_gw  [(size_t)BB*KS5*NNp];
__device__ __nv_bfloat16 d_wg[(size_t)2*KK9*CC*256];  // [slot][k][o][hi128|lo128]
__device__ __nv_bfloat16 d_wc[(size_t)2*KS5*CC*256];
__device__ float d_part[256*PROWS];
__device__ float d_colsum[256];

// ---------------- helpers ----------------
__device__ __forceinline__ uint32_t smem_u32(const void* p) {
    uint32_t a;
    asm("{ .reg .u64 t; cvta.to.shared.u64 t, %1; cvt.u32.u64 %0, t; }" : "=r"(a) : "l"(p));
    return a;
}

#define LDSM4(r, addr) \
    asm volatile("ldmatrix.sync.aligned.m8n8.x4.shared.b16 {%0,%1,%2,%3}, [%4];" \
        : "=r"((r)[0]), "=r"((r)[1]), "=r"((r)[2]), "=r"((r)[3]) : "r"(addr))
#define LDSM2(r, addr) \
    asm volatile("ldmatrix.sync.aligned.m8n8.x2.shared.b16 {%0,%1}, [%2];" \
        : "=r"((r)[0]), "=r"((r)[1]) : "r"(addr))
#define MMA_BF16(d, a, b) \
    asm volatile("mma.sync.aligned.m16n8k16.row.col.f32.bf16.bf16.f32 " \
        "{%0,%1,%2,%3}, {%4,%5,%6,%7}, {%8,%9}, {%0,%1,%2,%3};" \
        : "+f"((d)[0]), "+f"((d)[1]), "+f"((d)[2]), "+f"((d)[3]) \
        : "r"((a)[0]), "r"((a)[1]), "r"((a)[2]), "r"((a)[3]), "r"((b)[0]), "r"((b)[1]))
#define CP16(dst, src) \
    asm volatile("cp.async.cg.shared.global [%0], [%1], 16;" :: "r"(dst), "l"(src))
#define CP16Z(dst, src, sz) \
    asm volatile("cp.async.cg.shared.global [%0], [%1], 16, %2;" :: "r"(dst), "l"(src), "r"(sz))
#define CP_COMMIT() asm volatile("cp.async.commit_group;" ::: "memory")
#define CP_WAIT(n)  asm volatile("cp.async.wait_group %0;" :: "n"(n) : "memory")

// SMEM row = [hi 256B | lo 256B | pad 16B] = 528 B (conflict-free ldmatrix)
#define RS 528
#define A_BY   (128*RS)                 // 67584
#define W_BY   (128*RS)                 // 67584 (128 o-rows)
// gconv layout
#define G_W0   A_BY
#define G_W1   (A_BY + W_BY)
#define G_RED  (A_BY + 2*W_BY)          // 202752, 256 floats
#define G_IDX  (G_RED + 1024)           // 203776, 128*9 ints
#define SMEM_G (G_IDX + 128*KK9*4)      // 208384
// wconv layout (A = 132 rows)
#define AW_BY  (132*RS)                 // 69696
#define W_W0   AW_BY
#define W_W1   (AW_BY + W_BY)
#define W_RED  (AW_BY + 2*W_BY)         // 204864
#define SMEM_W (W_RED + 1024)           // 205888

// ---------------- shared compute: 8 k16-steps of bf16x3 mma ----------------
__device__ __forceinline__ void compute8(uint32_t aB, uint32_t wB,
    uint32_t aOff, uint32_t bOff, float acc[2][4][4])
{
#pragma unroll
    for (int kk = 0; kk < 8; kk++) {
        uint32_t ko = kk * 32;
        uint32_t ah[2][4], al[2][4], bh[4][2], bl[4][2];
#pragma unroll
        for (int mt = 0; mt < 2; mt++) {
            LDSM4(ah[mt], aB + aOff + mt*16*RS + ko);
            LDSM4(al[mt], aB + aOff + mt*16*RS + 256 + ko);
        }
#pragma unroll
        for (int ot = 0; ot < 4; ot++) {
            LDSM2(bh[ot], wB + bOff + ot*8*RS + ko);
            LDSM2(bl[ot], wB + bOff + ot*8*RS + 256 + ko);
        }
#pragma unroll
        for (int mt = 0; mt < 2; mt++)
#pragma unroll
            for (int ot = 0; ot < 4; ot++) {
                MMA_BF16(acc[mt][ot], ah[mt], bh[ot]);
                MMA_BF16(acc[mt][ot], ah[mt], bl[ot]);
                MMA_BF16(acc[mt][ot], al[mt], bh[ot]);
            }
    }
}

// ---------------- shared epilogue: store raw out + fused BN stats ----------------
__device__ __forceinline__ void epilogue(float acc[2][4][4], float* outb, float* red,
    int b, int n0, int nt, int wm, int wo, int lane, int tid)
{
#pragma unroll
    for (int ot = 0; ot < 4; ot++) {
        float s0 = 0.f, s1 = 0.f, q0 = 0.f, q1 = 0.f;
        int og = wo*32 + ot*8 + 2*(lane & 3);
#pragma unroll
        for (int mt = 0; mt < 2; mt++) {
            float c0 = acc[mt][ot][0], c1 = acc[mt][ot][1];
            float c2 = acc[mt][ot][2], c3 = acc[mt][ot][3];
            int n1 = n0 + wm*32 + mt*16 + (lane >> 2);
            float* o1 = outb + ((size_t)b*NNp + n1)*CC + og;
            *(float2*)o1          = make_float2(c0, c1);
            *(float2*)(o1 + 8*CC) = make_float2(c2, c3);
            s0 += c0 + c2;  s1 += c1 + c3;
            q0 += c0*c0 + c2*c2;  q1 += c1*c1 + c3*c3;
        }
#pragma unroll
        for (int m2 = 4; m2 <= 16; m2 <<= 1) {
            s0 += __shfl_xor_sync(0xffffffffu, s0, m2);
            s1 += __shfl_xor_sync(0xffffffffu, s1, m2);
            q0 += __shfl_xor_sync(0xffffffffu, q0, m2);
            q1 += __shfl_xor_sync(0xffffffffu, q1, m2);
        }
        if (lane < 4) {
            int o4 = wo*32 + ot*8 + 2*lane;
            atomicAdd(&red[o4],     s0);
            atomicAdd(&red[o4 + 1], s1);
            atomicAdd(&red[128 + o4],     q0);
            atomicAdd(&red[128 + o4 + 1], q1);
        }
    }
    __syncthreads();
    int row = b*256 + nt;
    if (tid < 256) d_part[(size_t)tid * PROWS + row] = red[tid];
}

// ---------------- gather conv: A reg-prefetch, W cp.async double-buffered ----------------
__global__ __launch_bounds__(512, 1) void k_gconv(int plSel, const int* __restrict__ eidx, int wSel)
{
    extern __shared__ char smem[];
    float* red = (float*)(smem + G_RED);
    int* sidx = (int*)(smem + G_IDX);

    int tid = threadIdx.x, lane = tid & 31, wid = tid >> 5;
    int wm = wid & 3, wo = wid >> 2;
    int nt = blockIdx.x, b = blockIdx.y;
    int n0 = nt * 128;

    const char* pl = (const char*)(plSel ? d_pl1 : d_pl0);
    const char* wsrc = (const char*)d_wg + (size_t)(wSel*KK9)*128*512;

    if (tid < 256) red[tid] = 0.0f;
    for (int i = tid; i < 128*KK9; i += 512)
        sidx[i] = eidx[((size_t)b*NNp + n0)*KK9 + i];
    __syncthreads();

    float acc[2][4][4];
#pragma unroll
    for (int mt = 0; mt < 2; mt++)
#pragma unroll
        for (int ot = 0; ot < 4; ot++)
#pragma unroll
            for (int q = 0; q < 4; q++) acc[mt][ot][q] = 0.0f;

    uint32_t aOff = (uint32_t)(wm*32 + (lane & 15))*RS + (lane >> 4)*16;
    uint32_t bOff = (uint32_t)(wo*32 + (lane & 7))*RS + ((lane >> 3) & 1)*16;
    uint32_t smB = smem_u32(smem);

    int r = tid >> 2, q4 = tid & 3;            // staging: row, 128B quarter
    uint32_t aDst = smB + (uint32_t)r*RS + q4*128;

    uint4 pf[8];
    // prefetch A(0)
    {
        const uint4* sa = (const uint4*)(pl + ((size_t)(b*NNp + sidx[r*KK9]))*512 + q4*128);
#pragma unroll
        for (int u = 0; u < 8; u++) pf[u] = sa[u];
    }
    // W(0), W(1) via cp.async
    {
        const char* sw = wsrc + (size_t)(0*128 + r)*512 + q4*128;
        uint32_t dw = smB + G_W0 + (uint32_t)r*RS + q4*128;
#pragma unroll
        for (int u = 0; u < 8; u++) CP16(dw + u*16, sw + u*16);
        CP_COMMIT();
        sw = wsrc + (size_t)(1*128 + r)*512 + q4*128;
        dw = smB + G_W1 + (uint32_t)r*RS + q4*128;
#pragma unroll
        for (int u = 0; u < 8; u++) CP16(dw + u*16, sw + u*16);
        CP_COMMIT();
    }
    // store A(0)
#pragma unroll
    for (int u = 0; u < 8; u++) *(uint4*)(smem + (aDst - smB) + u*16) = pf[u];
    CP_WAIT(1);
    __syncthreads();

    for (int k = 0; k < KK9; k++) {
        if (k + 1 < KK9) {
            const uint4* sa = (const uint4*)(pl + ((size_t)(b*NNp + sidx[r*KK9 + k + 1]))*512 + q4*128);
#pragma unroll
            for (int u = 0; u < 8; u++) pf[u] = sa[u];
        }
        uint32_t wB = smB + ((k & 1) ? G_W1 : G_W0);
        compute8(smB, wB, aOff, bOff, acc);
        __syncthreads();
        if (k + 1 < KK9) {
#pragma unroll
            for (int u = 0; u < 8; u++) *(uint4*)(smem + (aDst - smB) + u*16) = pf[u];
            if (k + 2 < KK9) {
                const char* sw = wsrc + (size_t)((k + 2)*128 + r)*512 + q4*128;
                uint32_t dw = smB + ((k & 1) ? G_W1 : G_W0) + (uint32_t)r*RS + q4*128;
#pragma unroll
                for (int u = 0; u < 8; u++) CP16(dw + u*16, sw + u*16);
                CP_COMMIT();
                CP_WAIT(1);
            } else {
                CP_WAIT(0);
            }
            __syncthreads();
        }
    }

    epilogue(acc, d_bufA, red, b, n0, nt, wm, wo, lane, tid);
}

// ---------------- weighted conv: A staged ONCE (132 rows), gw applied in fp32 ----------------
__global__ __launch_bounds__(512, 1) void k_wconv(int plSel, int wSel)
{
    extern __shared__ char smem[];
    float* red = (float*)(smem + W_RED);

    int tid = threadIdx.x, lane = tid & 31, wid = tid >> 5;
    int wm = wid & 3, wo = wid >> 2;
    int nt = blockIdx.x, b = blockIdx.y;
    int n0 = nt * 128;

    const char* pl = (const char*)(plSel ? d_pl1 : d_pl0);
    const char* wsrc = (const char*)d_wc + (size_t)(wSel*KS5)*128*512;
    const float* gwp = d_gw + (size_t)b*KS5*NNp;

    if (tid < 256) red[tid] = 0.0f;

    float acc[2][4][4];
#pragma unroll
    for (int mt = 0; mt < 2; mt++)
#pragma unroll
        for (int ot = 0; ot < 4; ot++)
#pragma unroll
            for (int q = 0; q < 4; q++) acc[mt][ot][q] = 0.0f;

    uint32_t aOff = (uint32_t)(wm*32 + (lane & 15))*RS + (lane >> 4)*16;
    uint32_t bOff = (uint32_t)(wo*32 + (lane & 7))*RS + ((lane >> 3) & 1)*16;
    uint32_t smB = smem_u32(smem);

    int r = tid >> 2, q4 = tid & 3;

    // stage A once: 132 rows (n0-2 .. n0+129), zero-fill out of range
    for (int i = tid; i < 132*4; i += 512) {
        int rr = i >> 2, qq = i & 3;
        int m = n0 + rr - 2;
        bool v = (m >= 0) && (m < NNp);
        const char* sa = pl + ((size_t)(b*NNp + (v ? m : 0)))*512 + qq*128;
        uint32_t da = smB + (uint32_t)rr*RS + qq*128;
        uint32_t sz = v ? 16u : 0u;
#pragma unroll
        for (int u = 0; u < 8; u++) CP16Z(da + u*16, sa + u*16, sz);
    }
    // W(0)
    {
        const char* sw = wsrc + (size_t)(0*128 + r)*512 + q4*128;
        uint32_t dw = smB + W_W0 + (uint32_t)r*RS + q4*128;
#pragma unroll
        for (int u = 0; u < 8; u++) CP16(dw + u*16, sw + u*16);
        CP_COMMIT();
    }
    // W(1)
    {
        const char* sw = wsrc + (size_t)(1*128 + r)*512 + q4*128;
        uint32_t dw = smB + W_W1 + (uint32_t)r*RS + q4*128;
#pragma unroll
        for (int u = 0; u < 8; u++) CP16(dw + u*16, sw + u*16);
        CP_COMMIT();
    }
    CP_WAIT(1);
    __syncthreads();

    int rowA = n0 + wm*32 + (lane >> 2);

    for (int k = 0; k < KS5; k++) {
        float P[2][4][4];
#pragma unroll
        for (int mt = 0; mt < 2; mt++)
#pragma unroll
            for (int ot = 0; ot < 4; ot++)
#pragma unroll
                for (int q = 0; q < 4; q++) P[mt][ot][q] = 0.0f;

        uint32_t wB = smB + ((k & 1) ? W_W1 : W_W0);
        compute8(smB + (uint32_t)k*RS, wB, aOff, bOff, P);

        // total += g[k, n] * P   (fp32, per accumulator row)
#pragma unroll
        for (int mt = 0; mt < 2; mt++) {
            float gA = gwp[(size_t)k*NNp + rowA + mt*16];
            float gB = gwp[(size_t)k*NNp + rowA + mt*16 + 8];
#pragma unroll
            for (int ot = 0; ot < 4; ot++) {
                acc[mt][ot][0] = fmaf(gA, P[mt][ot][0], acc[mt][ot][0]);
                acc[mt][ot][1] = fmaf(gA, P[mt][ot][1], acc[mt][ot][1]);
                acc[mt][ot][2] = fmaf(gB, P[mt][ot][2], acc[mt][ot][2]);
                acc[mt][ot][3] = fmaf(gB, P[mt][ot][3], acc[mt][ot][3]);
            }
        }
        __syncthreads();   // all warps done reading W buffer (k&1)
        if (k + 2 < KS5) {
            const char* sw = wsrc + (size_t)((k + 2)*128 + r)*512 + q4*128;
            uint32_t dw = smB + ((k & 1) ? W_W1 : W_W0) + (uint32_t)r*RS + q4*128;
#pragma unroll
            for (int u = 0; u < 8; u++) CP16(dw + u*16, sw + u*16);
            CP_COMMIT();
            CP_WAIT(1);
            __syncthreads();
        } else if (k + 1 < KS5) {
            CP_WAIT(0);
            __syncthreads();
        }
    }

    epilogue(acc, d_bufB, red, b, n0, nt, wm, wo, lane, tid);
}

// ---------------- split x [B,C,N] -> plane (transpose + bf16 hi/lo) ----------------
__global__ void k_splitX(const float* __restrict__ x, int dstSel) {
    __shared__ float tile[32][33];
    __nv_bfloat16* dst = dstSel ? d_pl1 : d_pl0;
    int b = blockIdx.z, c0 = blockIdx.y*32, n0 = blockIdx.x*32;
    int tx = threadIdx.x, ty = threadIdx.y;
#pragma unroll
    for (int j = 0; j < 4; j++)
        tile[ty + 8*j][tx] = x[((size_t)b*CC + c0 + ty + 8*j)*NNp + n0 + tx];
    __syncthreads();
#pragma unroll
    for (int j = 0; j < 4; j++) {
        int nl = ty + 8*j;
        float v = tile[tx][nl];
        __nv_bfloat16 h = __float2bfloat16(v);
        __nv_bfloat16 l = __float2bfloat16(v - __bfloat162float(h));
        size_t base = ((size_t)b*NNp + n0 + nl)*256 + c0 + tx;
        dst[base] = h;
        dst[base + 128] = l;
    }
}

// ---------------- split buffer [B,N,C] -> plane (BN+ReLU fold) ----------------
__global__ void k_split(int srcSel, int dstSel,
                        const float* __restrict__ gamma, const float* __restrict__ beta) {
    const float* src = srcSel ? d_bufB : d_bufA;
    __nv_bfloat16* dst = dstSel ? d_pl1 : d_pl0;
    int t = threadIdx.x;
    size_t bn = (size_t)blockIdx.x*8 + (t >> 5);
    int c = (t & 31)*4;
    float4 v = *(const float4*)(src + bn*CC + c);
    float z[4] = {v.x, v.y, v.z, v.w};
#pragma unroll
    for (int e = 0; e < 4; e++) {
        float s = d_colsum[c + e], q = d_colsum[128 + c + e];
        float mean = s * (1.0f/MTOT);
        float var  = q * (1.0f/MTOT) - mean*mean;
        float sc = gamma[c + e] * rsqrtf(var + EPSb);
        float sh = beta[c + e] - mean*sc;
        z[e] = fmaxf(0.0f, sc*z[e] + sh);
    }
    __nv_bfloat162 h0 = __floats2bfloat162_rn(z[0], z[1]);
    __nv_bfloat162 h1 = __floats2bfloat162_rn(z[2], z[3]);
    float l0 = z[0] - __low2float(h0), l1 = z[1] - __high2float(h0);
    float l2 = z[2] - __low2float(h1), l3 = z[3] - __high2float(h1);
    __nv_bfloat162 lo0 = __floats2bfloat162_rn(l0, l1);
    __nv_bfloat162 lo1 = __floats2bfloat162_rn(l2, l3);
    *(uint2*)(dst + bn*256 + c)       = make_uint2(*(uint32_t*)&h0,  *(uint32_t*)&h1);
    *(uint2*)(dst + bn*256 + 128 + c) = make_uint2(*(uint32_t*)&lo0, *(uint32_t*)&lo1);
}

// ---------------- gaussian window weights ----------------
__global__ void k_gw(const float* __restrict__ co) {
    int b = blockIdx.y;
    int n = blockIdx.x*256 + threadIdx.x;
    float c0 = co[((size_t)b*3 + 0)*NNp + n];
    float c1 = co[((size_t)b*3 + 1)*NNp + n];
    float c2 = co[((size_t)b*3 + 2)*NNp + n];
#pragma unroll
    for (int k = 0; k < KS5; k++) {
        int m = n + k - 2;
        float g = 0.0f;
        if (m >= 0 && m < NNp) {
            float dx = co[((size_t)b*3 + 0)*NNp + m] - c0;
            float dy = co[((size_t)b*3 + 1)*NNp + m] - c1;
            float dz = co[((size_t)b*3 + 2)*NNp + m] - c2;
            g = expf(-0.5f * (dx*dx + dy*dy + dz*dz));
        }
        d_gw[((size_t)b*KS5 + k)*NNp + n] = g;
    }
}

// -------- weight prep: [o][c][k] fp32 -> [k][o][hi128|lo128] bf16 --------
__global__ void k_prepW(const float* __restrict__ w, int KK, int isC, int slot) {
    int i = blockIdx.x*256 + threadIdx.x;
    if (i >= KK*16384) return;
    int k = i >> 14;
    int rem = i & 16383;
    int o = rem >> 7, c = rem & 127;
    float v = w[((size_t)o*CC + c)*KK + k];
    __nv_bfloat16 bh = __float2bfloat16(v);
    __nv_bfloat16 bl = __float2bfloat16(v - __bfloat162float(bh));
    __nv_bfloat16* base = (isC ? d_wc : d_wg) + ((size_t)(slot*KK + k)*128 + o)*256;
    base[c] = bh;
    base[128 + c] = bl;
}

// ---------------- BN partial reduction ----------------
__global__ void k_red() {
    __shared__ float sh[256];
    int col = blockIdx.x, tid = threadIdx.x;
    const float* p = d_part + (size_t)col * PROWS;
    float s = 0.0f;
    for (int i = tid; i < PROWS; i += 256) s += p[i];
    sh[tid] = s;
    __syncthreads();
    for (int st = 128; st > 0; st >>= 1) {
        if (tid < st) sh[tid] += sh[tid + st];
        __syncthreads();
    }
    if (tid == 0) d_colsum[col] = sh[0];
}

// ---------------- final: out = relu(BN(bufB) + x), back to [B,C,N] ----------------
__global__ void k_final(const float* __restrict__ x,
                        const float* __restrict__ gamma,
                        const float* __restrict__ beta,
                        float* __restrict__ out)
{
    __shared__ float tile[32][33];
    __shared__ float sc[32], sh[32];
    int b = blockIdx.z, c0 = blockIdx.y*32, n0 = blockIdx.x*32;
    int tx = threadIdx.x, ty = threadIdx.y;
    if (ty == 0) {
        int c = c0 + tx;
        float s = d_colsum[c], q = d_colsum[128 + c];
        float mean = s * (1.0f/MTOT);
        float var  = q * (1.0f/MTOT) - mean*mean;
        float a = gamma[c] * rsqrtf(var + EPSb);
        sc[tx] = a;
        sh[tx] = beta[c] - mean*a;
    }
    __syncthreads();
#pragma unroll
    for (int j = 0; j < 4; j++) {
        int n = n0 + ty + 8*j;
        float v = d_bufB[((size_t)b*NNp + n)*CC + c0 + tx];
        tile[ty + 8*j][tx] = sc[tx]*v + sh[tx];
    }
    __syncthreads();
#pragma unroll
    for (int j = 0; j < 4; j++) {
        int c = c0 + ty + 8*j;
        size_t o = ((size_t)b*CC + c)*NNp + n0 + tx;
        out[o] = fmaxf(0.0f, tile[tx][ty + 8*j] + x[o]);
    }
}

// ---------------- launch ----------------
extern "C" void kernel_launch(void* const* d_in, const int* in_sizes, int n_in,
                              void* d_out, int out_size)
{
    const float* x    = (const float*)d_in[0];
    const int*   ei   = (const int*)d_in[1];
    const float* co   = (const float*)d_in[2];
    const float* w2d1 = (const float*)d_in[3];
    const float* g2d1 = (const float*)d_in[4];
    const float* b2d1 = (const float*)d_in[5];
    const float* wc1  = (const float*)d_in[6];
    const float* g1d1 = (const float*)d_in[7];
    const float* b1d1 = (const float*)d_in[8];
    const float* w2d2 = (const float*)d_in[9];
    const float* g2d2 = (const float*)d_in[10];
    const float* b2d2 = (const float*)d_in[11];
    const float* wc2  = (const float*)d_in[12];
    const float* g1d2 = (const float*)d_in[13];
    const float* b1d2 = (const float*)d_in[14];
    float* out = (float*)d_out;

    cudaFuncSetAttribute(k_gconv, cudaFuncAttributeMaxDynamicSharedMemorySize, SMEM_G);
    cudaFuncSetAttribute(k_wconv, cudaFuncAttributeMaxDynamicSharedMemorySize, SMEM_W);

    dim3 g(256, BB);   // n-tile, batch

    // 5 pre-launches so launch #6 (ncu -s 5 -c 1) is gconv1
    k_gw<<<dim3(NNp/256, BB), 256>>>(co);
    k_splitX<<<dim3(NNp/32, CC/32, BB), dim3(32, 8)>>>(x, 0);
    k_prepW<<<(KK9*16384 + 255)/256, 256>>>(w2d1, KK9, 0, 0);
    k_prepW<<<(KS5*16384 + 255)/256, 256>>>(wc1,  KS5, 1, 0);
    k_prepW<<<(KK9*16384 + 255)/256, 256>>>(w2d2, KK9, 0, 1);

    // block 1
    k_gconv<<<g, 512, SMEM_G>>>(0, ei, 0);                    // pl0 -> bufA (+stats)
    k_prepW<<<(KS5*16384 + 255)/256, 256>>>(wc2,  KS5, 1, 1);
    k_red<<<256, 256>>>();
    k_split<<<BB*NNp/8, 256>>>(0, 1, g2d1, b2d1);             // bufA -> pl1 (BN+ReLU)
    k_wconv<<<g, 512, SMEM_W>>>(1, 0);                        // pl1 -> bufB (+stats)
    k_red<<<256, 256>>>();
    k_split<<<BB*NNp/8, 256>>>(1, 0, g1d1, b1d1);             // bufB -> pl0 (BN+ReLU)
    // block 2
    k_gconv<<<g, 512, SMEM_G>>>(0, ei, 1);                    // pl0 -> bufA (+stats)
    k_red<<<256, 256>>>();
    k_split<<<BB*NNp/8, 256>>>(0, 1, g2d2, b2d2);             // bufA -> pl1 (BN+ReLU)
    k_wconv<<<g, 512, SMEM_W>>>(1, 1);                        // pl1 -> bufB (+stats)
    k_red<<<256, 256>>>();
    // residual + relu + transpose back
    k_final<<<dim3(NNp/32, CC/32, BB), dim3(32, 8)>>>(x, g1d2, b1d2, out);
}

// round 12
// speedup vs baseline: 1.5554x; 1.5554x over previous
#include <cuda_runtime.h>
#include <cuda_bf16.h>
#include <math.h>
#include <stdint.h>

#define BB 4
#define CC 128
#define NNp 32768
#define KK9 9
#define KS5 5
#define EPSb 1e-5f
#define MTOT 131072.0f
#define PROWS 1024            // 256 n-tiles x 4 batches

// ---------------- scratch ----------------
__device__ __nv_bfloat16 d_pl0[(size_t)BB*NNp*256];   // planes [B,N, hi128|lo128]
__device__ __nv_bfloat16 d_pl1[(size_t)BB*NNp*256];
__device__ float d_bufA[(size_t)BB*NNp*CC];           // gconv raw out [B,N,C]
__device__ float d_bufB[(size_t)BB*NNp*CC];           // wconv raw out [B,N,C]
__device__ float d_gw  [(size_t)BB*KS5*NNp];
__device__ __nv_bfloat16 d_wg[(size_t)2*KK9*CC*256];  // [slot][k][o][hi128|lo128]
__device__ __nv_bfloat16 d_wc[(size_t)2*KS5*CC*256];
__device__ float d_part[256*PROWS];
__device__ float d_colsum[256];

// ---------------- helpers ----------------
__device__ __forceinline__ uint32_t smem_u32(const void* p) {
    uint32_t a;
    asm("{ .reg .u64 t; cvta.to.shared.u64 t, %1; cvt.u32.u64 %0, t; }" : "=r"(a) : "l"(p));
    return a;
}

#define LDSM4(r, addr) \
    asm volatile("ldmatrix.sync.aligned.m8n8.x4.shared.b16 {%0,%1,%2,%3}, [%4];" \
        : "=r"((r)[0]), "=r"((r)[1]), "=r"((r)[2]), "=r"((r)[3]) : "r"(addr))
#define LDSM2(r, addr) \
    asm volatile("ldmatrix.sync.aligned.m8n8.x2.shared.b16 {%0,%1}, [%2];" \
        : "=r"((r)[0]), "=r"((r)[1]) : "r"(addr))
#define MMA_BF16(d, a, b) \
    asm volatile("mma.sync.aligned.m16n8k16.row.col.f32.bf16.bf16.f32 " \
        "{%0,%1,%2,%3}, {%4,%5,%6,%7}, {%8,%9}, {%0,%1,%2,%3};" \
        : "+f"((d)[0]), "+f"((d)[1]), "+f"((d)[2]), "+f"((d)[3]) \
        : "r"((a)[0]), "r"((a)[1]), "r"((a)[2]), "r"((a)[3]), "r"((b)[0]), "r"((b)[1]))
#define CP16(dst, src) \
    asm volatile("cp.async.cg.shared.global [%0], [%1], 16;" :: "r"(dst), "l"(src))
#define CP16Z(dst, src, sz) \
    asm volatile("cp.async.cg.shared.global [%0], [%1], 16, %2;" :: "r"(dst), "l"(src), "r"(sz))
#define CP_COMMIT() asm volatile("cp.async.commit_group;" ::: "memory")
#define CP_WAIT(n)  asm volatile("cp.async.wait_group %0;" :: "n"(n) : "memory")

// SMEM row = [hi 256B | lo 256B | pad 16B] = 528 B (conflict-free ldmatrix)
#define RS 528
#define TB (128*RS)                  // 67584 per tile
// gconv layout: A0 | A1 | W | red | idx
#define G_A0   0
#define G_A1   TB
#define G_W    (2*TB)
#define G_RED  (3*TB)                // 202752, 256 floats
#define G_IDX  (G_RED + 1024)        // 203776
#define SMEM_G (G_IDX + 128*KK9*4)   // 208384
// wconv layout: A(132 rows) | W | red
#define AW_BY  (132*RS)              // 69696
#define W_W    AW_BY
#define W_RED  (AW_BY + TB)          // 137280
#define SMEM_W (W_RED + 1024)        // 138304

// ---------------- shared compute: 8 k16-steps of bf16x3 mma ----------------
__device__ __forceinline__ void compute8(uint32_t aB, uint32_t wB,
    uint32_t aOff, uint32_t bOff, float acc[2][4][4])
{
#pragma unroll
    for (int kk = 0; kk < 8; kk++) {
        uint32_t ko = kk * 32;
        uint32_t ah[2][4], al[2][4], bh[4][2], bl[4][2];
#pragma unroll
        for (int mt = 0; mt < 2; mt++) {
            LDSM4(ah[mt], aB + aOff + mt*16*RS + ko);
            LDSM4(al[mt], aB + aOff + mt*16*RS + 256 + ko);
        }
#pragma unroll
        for (int ot = 0; ot < 4; ot++) {
            LDSM2(bh[ot], wB + bOff + ot*8*RS + ko);
            LDSM2(bl[ot], wB + bOff + ot*8*RS + 256 + ko);
        }
#pragma unroll
        for (int mt = 0; mt < 2; mt++)
#pragma unroll
            for (int ot = 0; ot < 4; ot++) {
                MMA_BF16(acc[mt][ot], ah[mt], bh[ot]);
                MMA_BF16(acc[mt][ot], ah[mt], bl[ot]);
                MMA_BF16(acc[mt][ot], al[mt], bh[ot]);
            }
    }
}

// ---------------- shared epilogue: store raw out + fused BN stats ----------------
__device__ __forceinline__ void epilogue(float acc[2][4][4], float* outb, float* red,
    int b, int n0, int nt, int wm, int wo, int lane, int tid)
{
#pragma unroll
    for (int ot = 0; ot < 4; ot++) {
        float s0 = 0.f, s1 = 0.f, q0 = 0.f, q1 = 0.f;
        int og = wo*32 + ot*8 + 2*(lane & 3);
#pragma unroll
        for (int mt = 0; mt < 2; mt++) {
            float c0 = acc[mt][ot][0], c1 = acc[mt][ot][1];
            float c2 = acc[mt][ot][2], c3 = acc[mt][ot][3];
            int n1 = n0 + wm*32 + mt*16 + (lane >> 2);
            float* o1 = outb + ((size_t)b*NNp + n1)*CC + og;
            *(float2*)o1          = make_float2(c0, c1);
            *(float2*)(o1 + 8*CC) = make_float2(c2, c3);
            s0 += c0 + c2;  s1 += c1 + c3;
            q0 += c0*c0 + c2*c2;  q1 += c1*c1 + c3*c3;
        }
#pragma unroll
        for (int m2 = 4; m2 <= 16; m2 <<= 1) {
            s0 += __shfl_xor_sync(0xffffffffu, s0, m2);
            s1 += __shfl_xor_sync(0xffffffffu, s1, m2);
            q0 += __shfl_xor_sync(0xffffffffu, q0, m2);
            q1 += __shfl_xor_sync(0xffffffffu, q1, m2);
        }
        if (lane < 4) {
            int o4 = wo*32 + ot*8 + 2*lane;
            atomicAdd(&red[o4],     s0);
            atomicAdd(&red[o4 + 1], s1);
            atomicAdd(&red[128 + o4],     q0);
            atomicAdd(&red[128 + o4 + 1], q1);
        }
    }
    __syncthreads();
    int row = b*256 + nt;
    if (tid < 256) d_part[(size_t)tid * PROWS + row] = red[tid];
}

// ---------------- gather conv: A double-buffered cp.async, W serial restage ----------------
__global__ __launch_bounds__(512, 1) void k_gconv(int plSel, const int* __restrict__ eidx, int wSel)
{
    extern __shared__ char smem[];
    float* red = (float*)(smem + G_RED);
    int* sidx = (int*)(smem + G_IDX);

    int tid = threadIdx.x, lane = tid & 31, wid = tid >> 5;
    int wm = wid & 3, wo = wid >> 2;
    int nt = blockIdx.x, b = blockIdx.y;
    int n0 = nt * 128;

    const char* pl = (const char*)(plSel ? d_pl1 : d_pl0);
    const char* wsrc = (const char*)d_wg + (size_t)(wSel*KK9)*128*512;

    if (tid < 256) red[tid] = 0.0f;
    for (int i = tid; i < 128*KK9; i += 512)
        sidx[i] = eidx[((size_t)b*NNp + n0)*KK9 + i];
    __syncthreads();

    float acc[2][4][4];
#pragma unroll
    for (int mt = 0; mt < 2; mt++)
#pragma unroll
        for (int ot = 0; ot < 4; ot++)
#pragma unroll
            for (int q = 0; q < 4; q++) acc[mt][ot][q] = 0.0f;

    uint32_t aOff = (uint32_t)(wm*32 + (lane & 15))*RS + (lane >> 4)*16;
    uint32_t bOff = (uint32_t)(wo*32 + (lane & 7))*RS + ((lane >> 3) & 1)*16;
    uint32_t smB = smem_u32(smem);

    int r = tid >> 2, q4 = tid & 3;            // staging: row, 128B quarter
    uint32_t aSlot = (uint32_t)r*RS + q4*128;

    // issue A(k) gather into buffer buf (8x CP16 per thread, 64KB total)
#define ISSUE_A(k_, bufOff_) do { \
        const char* sa_ = pl + ((size_t)(b*NNp + sidx[r*KK9 + (k_)]))*512 + q4*128; \
        uint32_t da_ = smB + (bufOff_) + aSlot; \
        _Pragma("unroll") \
        for (int u_ = 0; u_ < 8; u_++) CP16(da_ + u_*16, sa_ + u_*16); \
        CP_COMMIT(); \
    } while (0)
#define ISSUE_W(k_) do { \
        const char* sw_ = wsrc + (size_t)((k_)*128 + r)*512 + q4*128; \
        uint32_t dw_ = smB + G_W + aSlot; \
        _Pragma("unroll") \
        for (int u_ = 0; u_ < 8; u_++) CP16(dw_ + u_*16, sw_ + u_*16); \
        CP_COMMIT(); \
    } while (0)

    ISSUE_A(0, G_A0);
    ISSUE_W(0);
    CP_WAIT(0);
    __syncthreads();

    for (int k = 0; k < KK9; k++) {
        // prefetch next A while computing (separate buffer, no reg cost)
        if (k + 1 < KK9) ISSUE_A(k + 1, (k & 1) ? G_A0 : G_A1);
        compute8(smB + ((k & 1) ? G_A1 : G_A0), smB + G_W, aOff, bOff, acc);
        __syncthreads();                  // all warps done with W(k) and A(k)
        if (k + 1 < KK9) {
            ISSUE_W(k + 1);               // serial W restage (L2 streaming)
            CP_WAIT(0);                   // A(k+1) + W(k+1) complete
            __syncthreads();
        }
    }
#undef ISSUE_A
#undef ISSUE_W

    epilogue(acc, d_bufA, red, b, n0, nt, wm, wo, lane, tid);
}

// ---------------- weighted conv: A staged once (132 rows), gw applied in fp32 ----------------
__global__ __launch_bounds__(512, 1) void k_wconv(int plSel, int wSel)
{
    extern __shared__ char smem[];
    float* red = (float*)(smem + W_RED);

    int tid = threadIdx.x, lane = tid & 31, wid = tid >> 5;
    int wm = wid & 3, wo = wid >> 2;
    int nt = blockIdx.x, b = blockIdx.y;
    int n0 = nt * 128;

    const char* pl = (const char*)(plSel ? d_pl1 : d_pl0);
    const char* wsrc = (const char*)d_wc + (size_t)(wSel*KS5)*128*512;
    const float* gwp = d_gw + (size_t)b*KS5*NNp;

    if (tid < 256) red[tid] = 0.0f;

    float acc[2][4][4];
#pragma unroll
    for (int mt = 0; mt < 2; mt++)
#pragma unroll
        for (int ot = 0; ot < 4; ot++)
#pragma unroll
            for (int q = 0; q < 4; q++) acc[mt][ot][q] = 0.0f;

    uint32_t aOff = (uint32_t)(wm*32 + (lane & 15))*RS + (lane >> 4)*16;
    uint32_t bOff = (uint32_t)(wo*32 + (lane & 7))*RS + ((lane >> 3) & 1)*16;
    uint32_t smB = smem_u32(smem);

    int r = tid >> 2, q4 = tid & 3;

    // stage A once: 132 rows (n0-2 .. n0+129), zero-fill out of range
    for (int i = tid; i < 132*4; i += 512) {
        int rr = i >> 2, qq = i & 3;
        int m = n0 + rr - 2;
        bool v = (m >= 0) && (m < NNp);
        const char* sa = pl + ((size_t)(b*NNp + (v ? m : 0)))*512 + qq*128;
        uint32_t da = smB + (uint32_t)rr*RS + qq*128;
        uint32_t sz = v ? 16u : 0u;
#pragma unroll
        for (int u = 0; u < 8; u++) CP16Z(da + u*16, sa + u*16, sz);
    }
    // W(0)
    {
        const char* sw = wsrc + (size_t)(0*128 + r)*512 + q4*128;
        uint32_t dw = smB + W_W + (uint32_t)r*RS + q4*128;
#pragma unroll
        for (int u = 0; u < 8; u++) CP16(dw + u*16, sw + u*16);
        CP_COMMIT();
    }
    CP_WAIT(0);
    __syncthreads();

    int rowA = n0 + wm*32 + (lane >> 2);

    for (int k = 0; k < KS5; k++) {
        float P[2][4][4];
#pragma unroll
        for (int mt = 0; mt < 2; mt++)
#pragma unroll
            for (int ot = 0; ot < 4; ot++)
#pragma unroll
                for (int q = 0; q < 4; q++) P[mt][ot][q] = 0.0f;

        compute8(smB + (uint32_t)k*RS, smB + W_W, aOff, bOff, P);

        // total += g[k, n] * P   (fp32, per accumulator row)
#pragma unroll
        for (int mt = 0; mt < 2; mt++) {
            float gA = gwp[(size_t)k*NNp + rowA + mt*16];
            float gB = gwp[(size_t)k*NNp + rowA + mt*16 + 8];
#pragma unroll
            for (int ot = 0; ot < 4; ot++) {
                acc[mt][ot][0] = fmaf(gA, P[mt][ot][0], acc[mt][ot][0]);
                acc[mt][ot][1] = fmaf(gA, P[mt][ot][1], acc[mt][ot][1]);
                acc[mt][ot][2] = fmaf(gB, P[mt][ot][2], acc[mt][ot][2]);
                acc[mt][ot][3] = fmaf(gB, P[mt][ot][3], acc[mt][ot][3]);
            }
        }
        __syncthreads();                  // all warps done reading W(k)
        if (k + 1 < KS5) {
            const char* sw = wsrc + (size_t)((k + 1)*128 + r)*512 + q4*128;
            uint32_t dw = smB + W_W + (uint32_t)r*RS + q4*128;
#pragma unroll
            for (int u = 0; u < 8; u++) CP16(dw + u*16, sw + u*16);
            CP_COMMIT();
            CP_WAIT(0);
            __syncthreads();
        }
    }

    epilogue(acc, d_bufB, red, b, n0, nt, wm, wo, lane, tid);
}

// ---------------- split x [B,C,N] -> plane (transpose + bf16 hi/lo) ----------------
__global__ void k_splitX(const float* __restrict__ x, int dstSel) {
    __shared__ float tile[32][33];
    __nv_bfloat16* dst = dstSel ? d_pl1 : d_pl0;
    int b = blockIdx.z, c0 = blockIdx.y*32, n0 = blockIdx.x*32;
    int tx = threadIdx.x, ty = threadIdx.y;
#pragma unroll
    for (int j = 0; j < 4; j++)
        tile[ty + 8*j][tx] = x[((size_t)b*CC + c0 + ty + 8*j)*NNp + n0 + tx];
    __syncthreads();
#pragma unroll
    for (int j = 0; j < 4; j++) {
        int nl = ty + 8*j;
        float v = tile[tx][nl];
        __nv_bfloat16 h = __float2bfloat16(v);
        __nv_bfloat16 l = __float2bfloat16(v - __bfloat162float(h));
        size_t base = ((size_t)b*NNp + n0 + nl)*256 + c0 + tx;
        dst[base] = h;
        dst[base + 128] = l;
    }
}

// ---------------- split buffer [B,N,C] -> plane (BN+ReLU fold) ----------------
__global__ void k_split(int srcSel, int dstSel,
                        const float* __restrict__ gamma, const float* __restrict__ beta) {
    const float* src = srcSel ? d_bufB : d_bufA;
    __nv_bfloat16* dst = dstSel ? d_pl1 : d_pl0;
    int t = threadIdx.x;
    size_t bn = (size_t)blockIdx.x*8 + (t >> 5);
    int c = (t & 31)*4;
    float4 v = *(const float4*)(src + bn*CC + c);
    float z[4] = {v.x, v.y, v.z, v.w};
#pragma unroll
    for (int e = 0; e < 4; e++) {
        float s = d_colsum[c + e], q = d_colsum[128 + c + e];
        float mean = s * (1.0f/MTOT);
        float var  = q * (1.0f/MTOT) - mean*mean;
        float sc = gamma[c + e] * rsqrtf(var + EPSb);
        float sh = beta[c + e] - mean*sc;
        z[e] = fmaxf(0.0f, sc*z[e] + sh);
    }
    __nv_bfloat162 h0 = __floats2bfloat162_rn(z[0], z[1]);
    __nv_bfloat162 h1 = __floats2bfloat162_rn(z[2], z[3]);
    float l0 = z[0] - __low2float(h0), l1 = z[1] - __high2float(h0);
    float l2 = z[2] - __low2float(h1), l3 = z[3] - __high2float(h1);
    __nv_bfloat162 lo0 = __floats2bfloat162_rn(l0, l1);
    __nv_bfloat162 lo1 = __floats2bfloat162_rn(l2, l3);
    *(uint2*)(dst + bn*256 + c)       = make_uint2(*(uint32_t*)&h0,  *(uint32_t*)&h1);
    *(uint2*)(dst + bn*256 + 128 + c) = make_uint2(*(uint32_t*)&lo0, *(uint32_t*)&lo1);
}

// ---------------- gaussian window weights ----------------
__global__ void k_gw(const float* __restrict__ co) {
    int b = blockIdx.y;
    int n = blockIdx.x*256 + threadIdx.x;
    float c0 = co[((size_t)b*3 + 0)*NNp + n];
    float c1 = co[((size_t)b*3 + 1)*NNp + n];
    float c2 = co[((size_t)b*3 + 2)*NNp + n];
#pragma unroll
    for (int k = 0; k < KS5; k++) {
        int m = n + k - 2;
        float g = 0.0f;
        if (m >= 0 && m < NNp) {
            float dx = co[((size_t)b*3 + 0)*NNp + m] - c0;
            float dy = co[((size_t)b*3 + 1)*NNp + m] - c1;
            float dz = co[((size_t)b*3 + 2)*NNp + m] - c2;
            g = expf(-0.5f * (dx*dx + dy*dy + dz*dz));
        }
        d_gw[((size_t)b*KS5 + k)*NNp + n] = g;
    }
}

// -------- weight prep: [o][c][k] fp32 -> [k][o][hi128|lo128] bf16 --------
__global__ void k_prepW(const float* __restrict__ w, int KK, int isC, int slot) {
    int i = blockIdx.x*256 + threadIdx.x;
    if (i >= KK*16384) return;
    int k = i >> 14;
    int rem = i & 16383;
    int o = rem >> 7, c = rem & 127;
    float v = w[((size_t)o*CC + c)*KK + k];
    __nv_bfloat16 bh = __float2bfloat16(v);
    __nv_bfloat16 bl = __float2bfloat16(v - __bfloat162float(bh));
    __nv_bfloat16* base = (isC ? d_wc : d_wg) + ((size_t)(slot*KK + k)*128 + o)*256;
    base[c] = bh;
    base[128 + c] = bl;
}

// ---------------- BN partial reduction ----------------
__global__ void k_red() {
    __shared__ float sh[256];
    int col = blockIdx.x, tid = threadIdx.x;
    const float* p = d_part + (size_t)col * PROWS;
    float s = 0.0f;
    for (int i = tid; i < PROWS; i += 256) s += p[i];
    sh[tid] = s;
    __syncthreads();
    for (int st = 128; st > 0; st >>= 1) {
        if (tid < st) sh[tid] += sh[tid + st];
        __syncthreads();
    }
    if (tid == 0) d_colsum[col] = sh[0];
}

// ---------------- final: out = relu(BN(bufB) + x), back to [B,C,N] ----------------
__global__ void k_final(const float* __restrict__ x,
                        const float* __restrict__ gamma,
                        const float* __restrict__ beta,
                        float* __restrict__ out)
{
    __shared__ float tile[32][33];
    __shared__ float sc[32], sh[32];
    int b = blockIdx.z, c0 = blockIdx.y*32, n0 = blockIdx.x*32;
    int tx = threadIdx.x, ty = threadIdx.y;
    if (ty == 0) {
        int c = c0 + tx;
        float s = d_colsum[c], q = d_colsum[128 + c];
        float mean = s * (1.0f/MTOT);
        float var  = q * (1.0f/MTOT) - mean*mean;
        float a = gamma[c] * rsqrtf(var + EPSb);
        sc[tx] = a;
        sh[tx] = beta[c] - mean*a;
    }
    __syncthreads();
#pragma unroll
    for (int j = 0; j < 4; j++) {
        int n = n0 + ty + 8*j;
        float v = d_bufB[((size_t)b*NNp + n)*CC + c0 + tx];
        tile[ty + 8*j][tx] = sc[tx]*v + sh[tx];
    }
    __syncthreads();
#pragma unroll
    for (int j = 0; j < 4; j++) {
        int c = c0 + ty + 8*j;
        size_t o = ((size_t)b*CC + c)*NNp + n0 + tx;
        out[o] = fmaxf(0.0f, tile[tx][ty + 8*j] + x[o]);
    }
}

// ---------------- launch ----------------
extern "C" void kernel_launch(void* const* d_in, const int* in_sizes, int n_in,
                              void* d_out, int out_size)
{
    const float* x    = (const float*)d_in[0];
    const int*   ei   = (const int*)d_in[1];
    const float* co   = (const float*)d_in[2];
    const float* w2d1 = (const float*)d_in[3];
    const float* g2d1 = (const float*)d_in[4];
    const float* b2d1 = (const float*)d_in[5];
    const float* wc1  = (const float*)d_in[6];
    const float* g1d1 = (const float*)d_in[7];
    const float* b1d1 = (const float*)d_in[8];
    const float* w2d2 = (const float*)d_in[9];
    const float* g2d2 = (const float*)d_in[10];
    const float* b2d2 = (const float*)d_in[11];
    const float* wc2  = (const float*)d_in[12];
    const float* g1d2 = (const float*)d_in[13];
    const float* b1d2 = (const float*)d_in[14];
    float* out = (float*)d_out;

    cudaFuncSetAttribute(k_gconv, cudaFuncAttributeMaxDynamicSharedMemorySize, SMEM_G);
    cudaFuncSetAttribute(k_wconv, cudaFuncAttributeMaxDynamicSharedMemorySize, SMEM_W);

    dim3 g(256, BB);   // n-tile, batch

    // Launch order puts the FIRST heavy GEMM at user-launch #4 —
    // cross-round evidence says that's the slot ncu captures.
    k_splitX<<<dim3(NNp/32, CC/32, BB), dim3(32, 8)>>>(x, 0);          // #1
    k_prepW<<<(KK9*16384 + 255)/256, 256>>>(w2d1, KK9, 0, 0);          // #2
    k_gw<<<dim3(NNp/256, BB), 256>>>(co);                              // #3

    // block 1
    k_gconv<<<g, 512, SMEM_G>>>(0, ei, 0);                             // #4  pl0 -> bufA
    k_red<<<256, 256>>>();                                             // #5
    k_split<<<BB*NNp/8, 256>>>(0, 1, g2d1, b2d1);                      // #6  bufA -> pl1
    k_prepW<<<(KS5*16384 + 255)/256, 256>>>(wc1,  KS5, 1, 0);          // #7
    k_wconv<<<g, 512, SMEM_W>>>(1, 0);                                 // #8  pl1 -> bufB
    k_red<<<256, 256>>>();
    k_split<<<BB*NNp/8, 256>>>(1, 0, g1d1, b1d1);                      // bufB -> pl0
    // block 2
    k_prepW<<<(KK9*16384 + 255)/256, 256>>>(w2d2, KK9, 0, 1);
    k_gconv<<<g, 512, SMEM_G>>>(0, ei, 1);                             // pl0 -> bufA
    k_red<<<256, 256>>>();
    k_split<<<BB*NNp/8, 256>>>(0, 1, g2d2, b2d2);                      // bufA -> pl1
    k_prepW<<<(KS5*16384 + 255)/256, 256>>>(wc2,  KS5, 1, 1);
    k_wconv<<<g, 512, SMEM_W>>>(1, 1);                                 // pl1 -> bufB
    k_red<<<256, 256>>>();
    // residual + relu + transpose back
    k_final<<<dim3(NNp/32, CC/32, BB), dim3(32, 8)>>>(x, g1d2, b1d2, out);
}

// round 15
// speedup vs baseline: 2.3292x; 1.4975x over previous
#include <cuda_runtime.h>
#include <cuda_bf16.h>
#include <math.h>
#include <stdint.h>

#define BB 4
#define CC 128
#define NNp 32768
#define KK9 9
#define KS5 5
#define EPSb 1e-5f
#define MTOT 131072.0f
#define PROWS 1024            // 256 n-tiles x 4 batches

// ---------------- scratch ----------------
__device__ __nv_bfloat16 d_pl0[(size_t)BB*NNp*256];   // planes [B,N, hi128|lo128]
__device__ __nv_bfloat16 d_pl1[(size_t)BB*NNp*256];
__device__ float d_bufA[(size_t)BB*NNp*CC];           // gconv raw out [B,N,C]
__device__ float d_bufB[(size_t)BB*NNp*CC];           // wconv raw out [B,N,C]
__device__ float d_gw  [(size_t)BB*KS5*NNp];
__device__ __nv_bfloat16 d_wg[(size_t)2*KK9*CC*256];  // [slot][k][o][hi128|lo128]
__device__ __nv_bfloat16 d_wc[(size_t)2*KS5*CC*256];
__device__ float d_part[256*PROWS];
__device__ float d_colsum[256];

// ---------------- helpers ----------------
__device__ __forceinline__ uint32_t smem_u32(const void* p) {
    uint32_t a;
    asm("{ .reg .u64 t; cvta.to.shared.u64 t, %1; cvt.u32.u64 %0, t; }" : "=r"(a) : "l"(p));
    return a;
}

#define LDSM4(r, addr) \
    asm volatile("ldmatrix.sync.aligned.m8n8.x4.shared.b16 {%0,%1,%2,%3}, [%4];" \
        : "=r"((r)[0]), "=r"((r)[1]), "=r"((r)[2]), "=r"((r)[3]) : "r"(addr))
#define MMA_BF16(d, a, b) \
    asm volatile("mma.sync.aligned.m16n8k16.row.col.f32.bf16.bf16.f32 " \
        "{%0,%1,%2,%3}, {%4,%5,%6,%7}, {%8,%9}, {%0,%1,%2,%3};" \
        : "+f"((d)[0]), "+f"((d)[1]), "+f"((d)[2]), "+f"((d)[3]) \
        : "r"((a)[0]), "r"((a)[1]), "r"((a)[2]), "r"((a)[3]), "r"((b)[0]), "r"((b)[1]))
#define CP16(dst, src) \
    asm volatile("cp.async.cg.shared.global [%0], [%1], 16;" :: "r"(dst), "l"(src))
#define CP16Z(dst, src, sz) \
    asm volatile("cp.async.cg.shared.global [%0], [%1], 16, %2;" :: "r"(dst), "l"(src), "r"(sz))
#define CP_COMMIT() asm volatile("cp.async.commit_group;" ::: "memory")
#define CP_WAIT(n)  asm volatile("cp.async.wait_group %0;" :: "n"(n) : "memory")

// SMEM row = [hi 256B | lo 256B | pad 16B] = 528 B (conflict-free ldmatrix)
#define RS 528
// gconv layout: A(128) | W(64) | red | idx   -> 2 CTAs/SM
#define G_W    (128*RS)              // 67584
#define G_RED  (G_W + 64*RS)         // 101376, 128 floats
#define G_IDX  (G_RED + 512)         // 101888
#define SMEM_G (G_IDX + 128*KK9*4)   // 106496
// wconv layout: A(132) | W(64) | red        -> 2 CTAs/SM
#define W_W    (132*RS)              // 69696
#define W_RED  (W_W + 64*RS)         // 103488
#define SMEM_W (W_RED + 512)         // 104000

// ---------------- compute: 8 k16-steps of bf16x3 mma (tile 128x64, 8 warps) ----------------
// B hi/lo fragments merged into one LDSM4 (lanes 16-31 read the lo plane at +256).
__device__ __forceinline__ void compute8(uint32_t aB, uint32_t wB,
    uint32_t aOff, uint32_t bOff, float acc[2][4][4])
{
#pragma unroll
    for (int kk = 0; kk < 8; kk++) {
        uint32_t ko = kk * 32;
        uint32_t ah[2][4], al[2][4], bf[4][4];
#pragma unroll
        for (int mt = 0; mt < 2; mt++) {
            LDSM4(ah[mt], aB + aOff + mt*16*RS + ko);
            LDSM4(al[mt], aB + aOff + mt*16*RS + 256 + ko);
        }
#pragma unroll
        for (int ot = 0; ot < 4; ot++)
            LDSM4(bf[ot], wB + bOff + ot*8*RS + ko);
#pragma unroll
        for (int mt = 0; mt < 2; mt++)
#pragma unroll
            for (int ot = 0; ot < 4; ot++) {
                MMA_BF16(acc[mt][ot], ah[mt], &bf[ot][0]);   // Ah*Bh
                MMA_BF16(acc[mt][ot], ah[mt], &bf[ot][2]);   // Ah*Bl
                MMA_BF16(acc[mt][ot], al[mt], &bf[ot][0]);   // Al*Bh
            }
    }
}

// ---------------- epilogue: store raw out + fused BN stats (o-half aware) ----------------
__device__ __forceinline__ void epilogue(float acc[2][4][4], float* outb, float* red,
    int b, int n0, int oh, int nt, int wm, int wo, int lane, int tid)
{
#pragma unroll
    for (int ot = 0; ot < 4; ot++) {
        float s0 = 0.f, s1 = 0.f, q0 = 0.f, q1 = 0.f;
        int og = oh*64 + wo*32 + ot*8 + 2*(lane & 3);
#pragma unroll
        for (int mt = 0; mt < 2; mt++) {
            float c0 = acc[mt][ot][0], c1 = acc[mt][ot][1];
            float c2 = acc[mt][ot][2], c3 = acc[mt][ot][3];
            int n1 = n0 + wm*32 + mt*16 + (lane >> 2);
            float* o1 = outb + ((size_t)b*NNp + n1)*CC + og;
            *(float2*)o1          = make_float2(c0, c1);
            *(float2*)(o1 + 8*CC) = make_float2(c2, c3);
            s0 += c0 + c2;  s1 += c1 + c3;
            q0 += c0*c0 + c2*c2;  q1 += c1*c1 + c3*c3;
        }
#pragma unroll
        for (int m2 = 4; m2 <= 16; m2 <<= 1) {
            s0 += __shfl_xor_sync(0xffffffffu, s0, m2);
            s1 += __shfl_xor_sync(0xffffffffu, s1, m2);
            q0 += __shfl_xor_sync(0xffffffffu, q0, m2);
            q1 += __shfl_xor_sync(0xffffffffu, q1, m2);
        }
        if (lane < 4) {
            int o4 = wo*32 + ot*8 + 2*lane;
            atomicAdd(&red[o4],     s0);
            atomicAdd(&red[o4 + 1], s1);
            atomicAdd(&red[64 + o4],     q0);
            atomicAdd(&red[64 + o4 + 1], q1);
        }
    }
    __syncthreads();
    int row = b*256 + nt;
    if (tid < 128) {
        int isq = tid >> 6, ol = tid & 63;
        d_part[((size_t)(isq*128 + oh*64 + ol))*PROWS + row] = red[isq*64 + ol];
    }
}

// ---------------- gather conv: 128x64 tile, warp-contiguous cp.async staging ----------------
__global__ __launch_bounds__(256, 2) void k_gconv(int plSel, const int* __restrict__ eidx, int wSel)
{
    extern __shared__ char smem[];
    float* red = (float*)(smem + G_RED);
    int* sidx = (int*)(smem + G_IDX);

    int tid = threadIdx.x, lane = tid & 31, wid = tid >> 5;
    int wm = wid & 3, wo = wid >> 2;                 // 4 x 2 warp grid
    int nt = blockIdx.x, oh = blockIdx.y, b = blockIdx.z;
    int n0 = nt * 128;

    const char* pl = (const char*)(plSel ? d_pl1 : d_pl0);
    const char* wsrc = (const char*)d_wg + (size_t)(wSel*KK9)*128*512;

    if (tid < 128) red[tid] = 0.0f;
    for (int i = tid; i < 128*KK9; i += 256)
        sidx[i] = eidx[((size_t)b*NNp + n0)*KK9 + i];
    __syncthreads();

    float acc[2][4][4];
#pragma unroll
    for (int mt = 0; mt < 2; mt++)
#pragma unroll
        for (int ot = 0; ot < 4; ot++)
#pragma unroll
            for (int q = 0; q < 4; q++) acc[mt][ot][q] = 0.0f;

    uint32_t aOff = (uint32_t)(wm*32 + (lane & 15))*RS + (lane >> 4)*16;
    uint32_t bOff = (uint32_t)(wo*32 + (lane & 7))*RS + ((lane >> 3) & 1)*16 + (lane >> 4)*256;
    uint32_t smB = smem_u32(smem);

    // stage A(k): each warp stages 16 rows; one CP16 instruction = one full 512B row
#define STAGE_A(k_) do { \
        _Pragma("unroll") \
        for (int u_ = 0; u_ < 16; u_++) { \
            int rr_ = wid*16 + u_; \
            const char* sa_ = pl + ((size_t)(b*NNp + sidx[rr_*KK9 + (k_)]))*512 + lane*16; \
            CP16(smB + (uint32_t)rr_*RS + lane*16, sa_); \
        } \
    } while (0)
    // stage W(k): each warp stages 8 rows (64 o-rows of this o-half)
#define STAGE_W(k_) do { \
        _Pragma("unroll") \
        for (int u_ = 0; u_ < 8; u_++) { \
            int rr_ = wid*8 + u_; \
            const char* sw_ = wsrc + ((size_t)((k_)*128 + oh*64 + rr_))*512 + lane*16; \
            CP16(smB + G_W + (uint32_t)rr_*RS + lane*16, sw_); \
        } \
    } while (0)

    STAGE_A(0); STAGE_W(0); CP_COMMIT();
    CP_WAIT(0);
    __syncthreads();

    for (int k = 0; k < KK9; k++) {
        compute8(smB, smB + G_W, aOff, bOff, acc);
        __syncthreads();                  // all warps done with A(k), W(k)
        if (k + 1 < KK9) {
            STAGE_A(k + 1); STAGE_W(k + 1); CP_COMMIT();
            CP_WAIT(0);
            __syncthreads();
        }
    }
#undef STAGE_A
#undef STAGE_W

    epilogue(acc, d_bufA, red, b, n0, oh, nt, wm, wo, lane, tid);
}

// ---------------- weighted conv: A staged once (132 rows), gw in fp32 post-GEMM ----------------
__global__ __launch_bounds__(256, 2) void k_wconv(int plSel, int wSel)
{
    extern __shared__ char smem[];
    float* red = (float*)(smem + W_RED);

    int tid = threadIdx.x, lane = tid & 31, wid = tid >> 5;
    int wm = wid & 3, wo = wid >> 2;
    int nt = blockIdx.x, oh = blockIdx.y, b = blockIdx.z;
    int n0 = nt * 128;

    const char* pl = (const char*)(plSel ? d_pl1 : d_pl0);
    const char* wsrc = (const char*)d_wc + (size_t)(wSel*KS5)*128*512;
    const float* gwp = d_gw + (size_t)b*KS5*NNp;

    if (tid < 128) red[tid] = 0.0f;

    float acc[2][4][4];
#pragma unroll
    for (int mt = 0; mt < 2; mt++)
#pragma unroll
        for (int ot = 0; ot < 4; ot++)
#pragma unroll
            for (int q = 0; q < 4; q++) acc[mt][ot][q] = 0.0f;

    uint32_t aOff = (uint32_t)(wm*32 + (lane & 15))*RS + (lane >> 4)*16;
    uint32_t bOff = (uint32_t)(wo*32 + (lane & 7))*RS + ((lane >> 3) & 1)*16 + (lane >> 4)*256;
    uint32_t smB = smem_u32(smem);

    // stage A once: 132 rows (n0-2 .. n0+129), warp-contiguous, zero-fill OOB
    for (int rr = wid; rr < 132; rr += 8) {
        int m = n0 + rr - 2;
        bool v = (m >= 0) && (m < NNp);
        const char* sa = pl + ((size_t)(b*NNp + (v ? m : 0)))*512 + lane*16;
        CP16Z(smB + (uint32_t)rr*RS + lane*16, sa, v ? 16u : 0u);
    }
#define STAGE_WC(k_) do { \
        _Pragma("unroll") \
        for (int u_ = 0; u_ < 8; u_++) { \
            int rr_ = wid*8 + u_; \
            const char* sw_ = wsrc + ((size_t)((k_)*128 + oh*64 + rr_))*512 + lane*16; \
            CP16(smB + W_W + (uint32_t)rr_*RS + lane*16, sw_); \
        } \
    } while (0)
    STAGE_WC(0); CP_COMMIT();
    CP_WAIT(0);
    __syncthreads();

    int rowA = n0 + wm*32 + (lane >> 2);

    for (int k = 0; k < KS5; k++) {
        float P[2][4][4];
#pragma unroll
        for (int mt = 0; mt < 2; mt++)
#pragma unroll
            for (int ot = 0; ot < 4; ot++)
#pragma unroll
                for (int q = 0; q < 4; q++) P[mt][ot][q] = 0.0f;

        compute8(smB + (uint32_t)k*RS, smB + W_W, aOff, bOff, P);

        // total += g[k, n] * P   (fp32, per accumulator row)
#pragma unroll
        for (int mt = 0; mt < 2; mt++) {
            float gA = gwp[(size_t)k*NNp + rowA + mt*16];
            float gB = gwp[(size_t)k*NNp + rowA + mt*16 + 8];
#pragma unroll
            for (int ot = 0; ot < 4; ot++) {
                acc[mt][ot][0] = fmaf(gA, P[mt][ot][0], acc[mt][ot][0]);
                acc[mt][ot][1] = fmaf(gA, P[mt][ot][1], acc[mt][ot][1]);
                acc[mt][ot][2] = fmaf(gB, P[mt][ot][2], acc[mt][ot][2]);
                acc[mt][ot][3] = fmaf(gB, P[mt][ot][3], acc[mt][ot][3]);
            }
        }
        __syncthreads();                  // all warps done reading W(k)
        if (k + 1 < KS5) {
            STAGE_WC(k + 1); CP_COMMIT();
            CP_WAIT(0);
            __syncthreads();
        }
    }
#undef STAGE_WC

    epilogue(acc, d_bufB, red, b, n0, oh, nt, wm, wo, lane, tid);
}

// ---------------- split x [B,C,N] -> plane (transpose + bf16 hi/lo) ----------------
__global__ void k_splitX(const float* __restrict__ x, int dstSel) {
    __shared__ float tile[32][33];
    __nv_bfloat16* dst = dstSel ? d_pl1 : d_pl0;
    int b = blockIdx.z, c0 = blockIdx.y*32, n0 = blockIdx.x*32;
    int tx = threadIdx.x, ty = threadIdx.y;
#pragma unroll
    for (int j = 0; j < 4; j++)
        tile[ty + 8*j][tx] = x[((size_t)b*CC + c0 + ty + 8*j)*NNp + n0 + tx];
    __syncthreads();
#pragma unroll
    for (int j = 0; j < 4; j++) {
        int nl = ty + 8*j;
        float v = tile[tx][nl];
        __nv_bfloat16 h = __float2bfloat16(v);
        __nv_bfloat16 l = __float2bfloat16(v - __bfloat162float(h));
        size_t base = ((size_t)b*NNp + n0 + nl)*256 + c0 + tx;
        dst[base] = h;
        dst[base + 128] = l;
    }
}

// ---------------- split buffer [B,N,C] -> plane (BN+ReLU fold) ----------------
__global__ void k_split(int srcSel, int dstSel,
                        const float* __restrict__ gamma, const float* __restrict__ beta) {
    const float* src = srcSel ? d_bufB : d_bufA;
    __nv_bfloat16* dst = dstSel ? d_pl1 : d_pl0;
    int t = threadIdx.x;
    size_t bn = (size_t)blockIdx.x*8 + (t >> 5);
    int c = (t & 31)*4;
    float4 v = *(const float4*)(src + bn*CC + c);
    float z[4] = {v.x, v.y, v.z, v.w};
#pragma unroll
    for (int e = 0; e < 4; e++) {
        float s = d_colsum[c + e], q = d_colsum[128 + c + e];
        float mean = s * (1.0f/MTOT);
        float var  = q * (1.0f/MTOT) - mean*mean;
        float sc = gamma[c + e] * rsqrtf(var + EPSb);
        float sh = beta[c + e] - mean*sc;
        z[e] = fmaxf(0.0f, sc*z[e] + sh);
    }
    __nv_bfloat162 h0 = __floats2bfloat162_rn(z[0], z[1]);
    __nv_bfloat162 h1 = __floats2bfloat162_rn(z[2], z[3]);
    float l0 = z[0] - __low2float(h0), l1 = z[1] - __high2float(h0);
    float l2 = z[2] - __low2float(h1), l3 = z[3] - __high2float(h1);
    __nv_bfloat162 lo0 = __floats2bfloat162_rn(l0, l1);
    __nv_bfloat162 lo1 = __floats2bfloat162_rn(l2, l3);
    *(uint2*)(dst + bn*256 + c)       = make_uint2(*(uint32_t*)&h0,  *(uint32_t*)&h1);
    *(uint2*)(dst + bn*256 + 128 + c) = make_uint2(*(uint32_t*)&lo0, *(uint32_t*)&lo1);
}

// ---------------- gaussian window weights ----------------
__global__ void k_gw(const float* __restrict__ co) {
    int b = blockIdx.y;
    int n = blockIdx.x*256 + threadIdx.x;
    float c0 = co[((size_t)b*3 + 0)*NNp + n];
    float c1 = co[((size_t)b*3 + 1)*NNp + n];
    float c2 = co[((size_t)b*3 + 2)*NNp + n];
#pragma unroll
    for (int k = 0; k < KS5; k++) {
        int m = n + k - 2;
        float g = 0.0f;
        if (m >= 0 && m < NNp) {
            float dx = co[((size_t)b*3 + 0)*NNp + m] - c0;
            float dy = co[((size_t)b*3 + 1)*NNp + m] - c1;
            float dz = co[((size_t)b*3 + 2)*NNp + m] - c2;
            g = expf(-0.5f * (dx*dx + dy*dy + dz*dz));
        }
        d_gw[((size_t)b*KS5 + k)*NNp + n] = g;
    }
}

// -------- weight prep: [o][c][k] fp32 -> [k][o][hi128|lo128] bf16 --------
__global__ void k_prepW(const float* __restrict__ w, int KK, int isC, int slot) {
    int i = blockIdx.x*256 + threadIdx.x;
    if (i >= KK*16384) return;
    int k = i >> 14;
    int rem = i & 16383;
    int o = rem >> 7, c = rem & 127;
    float v = w[((size_t)o*CC + c)*KK + k];
    __nv_bfloat16 bh = __float2bfloat16(v);
    __nv_bfloat16 bl = __float2bfloat16(v - __bfloat162float(bh));
    __nv_bfloat16* base = (isC ? d_wc : d_wg) + ((size_t)(slot*KK + k)*128 + o)*256;
    base[c] = bh;
    base[128 + c] = bl;
}

// ---------------- BN partial reduction ----------------
__global__ void k_red() {
    __shared__ float sh[256];
    int col = blockIdx.x, tid = threadIdx.x;
    const float* p = d_part + (size_t)col * PROWS;
    float s = 0.0f;
    for (int i = tid; i < PROWS; i += 256) s += p[i];
    sh[tid] = s;
    __syncthreads();
    for (int st = 128; st > 0; st >>= 1) {
        if (tid < st) sh[tid] += sh[tid + st];
        __syncthreads();
    }
    if (tid == 0) d_colsum[col] = sh[0];
}

// ---------------- final: out = relu(BN(bufB) + x), back to [B,C,N] ----------------
__global__ void k_final(const float* __restrict__ x,
                        const float* __restrict__ gamma,
                        const float* __restrict__ beta,
                        float* __restrict__ out)
{
    __shared__ float tile[32][33];
    __shared__ float sc[32], sh[32];
    int b = blockIdx.z, c0 = blockIdx.y*32, n0 = blockIdx.x*32;
    int tx = threadIdx.x, ty = threadIdx.y;
    if (ty == 0) {
        int c = c0 + tx;
        float s = d_colsum[c], q = d_colsum[128 + c];
        float mean = s * (1.0f/MTOT);
        float var  = q * (1.0f/MTOT) - mean*mean;
        float a = gamma[c] * rsqrtf(var + EPSb);
        sc[tx] = a;
        sh[tx] = beta[c] - mean*a;
    }
    __syncthreads();
#pragma unroll
    for (int j = 0; j < 4; j++) {
        int n = n0 + ty + 8*j;
        float v = d_bufB[((size_t)b*NNp + n)*CC + c0 + tx];
        tile[ty + 8*j][tx] = sc[tx]*v + sh[tx];
    }
    __syncthreads();
#pragma unroll
    for (int j = 0; j < 4; j++) {
        int c = c0 + ty + 8*j;
        size_t o = ((size_t)b*CC + c)*NNp + n0 + tx;
        out[o] = fmaxf(0.0f, tile[tx][ty + 8*j] + x[o]);
    }
}

// ---------------- launch ----------------
extern "C" void kernel_launch(void* const* d_in, const int* in_sizes, int n_in,
                              void* d_out, int out_size)
{
    const float* x    = (const float*)d_in[0];
    const int*   ei   = (const int*)d_in[1];
    const float* co   = (const float*)d_in[2];
    const float* w2d1 = (const float*)d_in[3];
    const float* g2d1 = (const float*)d_in[4];
    const float* b2d1 = (const float*)d_in[5];
    const float* wc1  = (const float*)d_in[6];
    const float* g1d1 = (const float*)d_in[7];
    const float* b1d1 = (const float*)d_in[8];
    const float* w2d2 = (const float*)d_in[9];
    const float* g2d2 = (const float*)d_in[10];
    const float* b2d2 = (const float*)d_in[11];
    const float* wc2  = (const float*)d_in[12];
    const float* g1d2 = (const float*)d_in[13];
    const float* b1d2 = (const float*)d_in[14];
    float* out = (float*)d_out;

    cudaFuncSetAttribute(k_gconv, cudaFuncAttributeMaxDynamicSharedMemorySize, SMEM_G);
    cudaFuncSetAttribute(k_wconv, cudaFuncAttributeMaxDynamicSharedMemorySize, SMEM_W);

    dim3 g(256, 2, BB);   // n-tile, o-half, batch -> 2048 CTAs, 2 per SM

    // first heavy GEMM at user-launch #4 (the ncu-captured slot)
    k_splitX<<<dim3(NNp/32, CC/32, BB), dim3(32, 8)>>>(x, 0);          // #1
    k_prepW<<<(KK9*16384 + 255)/256, 256>>>(w2d1, KK9, 0, 0);          // #2
    k_gw<<<dim3(NNp/256, BB), 256>>>(co);                              // #3

    // block 1
    k_gconv<<<g, 256, SMEM_G>>>(0, ei, 0);                             // #4  pl0 -> bufA
    k_red<<<256, 256>>>();
    k_split<<<BB*NNp/8, 256>>>(0, 1, g2d1, b2d1);                      // bufA -> pl1
    k_prepW<<<(KS5*16384 + 255)/256, 256>>>(wc1,  KS5, 1, 0);
    k_wconv<<<g, 256, SMEM_W>>>(1, 0);                                 // pl1 -> bufB
    k_red<<<256, 256>>>();
    k_split<<<BB*NNp/8, 256>>>(1, 0, g1d1, b1d1);                      // bufB -> pl0
    // block 2
    k_prepW<<<(KK9*16384 + 255)/256, 256>>>(w2d2, KK9, 0, 1);
    k_gconv<<<g, 256, SMEM_G>>>(0, ei, 1);                             // pl0 -> bufA
    k_red<<<256, 256>>>();
    k_split<<<BB*NNp/8, 256>>>(0, 1, g2d2, b2d2);                      // bufA -> pl1
    k_prepW<<<(KS5*16384 + 255)/256, 256>>>(wc2,  KS5, 1, 1);
    k_wconv<<<g, 256, SMEM_W>>>(1, 1);                                 // pl1 -> bufB
    k_red<<<256, 256>>>();
    // residual + relu + transpose back
    k_final<<<dim3(NNp/32, CC/32, BB), dim3(32, 8)>>>(x, g1d2, b1d2, out);
}

// round 16
// speedup vs baseline: 4.1498x; 1.7817x over previous
#include <cuda_runtime.h>
#include <cuda_fp16.h>
#include <math.h>
#include <stdint.h>

#define BB 4
#define CC 128
#define NNp 32768
#define KK9 9
#define KS5 5
#define EPSb 1e-5f
#define MTOT 131072.0f
#define PROWS 1024            // 256 n-tiles x 4 batches

// ---------------- scratch ----------------
__device__ __half d_pl0[(size_t)BB*NNp*128];   // fp16 plane [B,N,C]
__device__ __half d_pl1[(size_t)BB*NNp*128];
__device__ float d_bufA[(size_t)BB*NNp*CC];    // gconv raw out [B,N,C]
__device__ float d_bufB[(size_t)BB*NNp*CC];    // wconv raw out [B,N,C]
__device__ float d_gw  [(size_t)BB*KS5*NNp];
__device__ __half d_wg[(size_t)2*KK9*CC*CC];   // [slot][k][o][c] fp16
__device__ __half d_wc[(size_t)2*KS5*CC*CC];
__device__ float d_part[256*PROWS];
__device__ float d_colsum[256];

// ---------------- helpers ----------------
__device__ __forceinline__ uint32_t smem_u32(const void* p) {
    uint32_t a;
    asm("{ .reg .u64 t; cvta.to.shared.u64 t, %1; cvt.u32.u64 %0, t; }" : "=r"(a) : "l"(p));
    return a;
}

#define LDSM4(r, addr) \
    asm volatile("ldmatrix.sync.aligned.m8n8.x4.shared.b16 {%0,%1,%2,%3}, [%4];" \
        : "=r"((r)[0]), "=r"((r)[1]), "=r"((r)[2]), "=r"((r)[3]) : "r"(addr))
#define MMA_F16(d, a, b0, b1) \
    asm volatile("mma.sync.aligned.m16n8k16.row.col.f32.f16.f16.f32 " \
        "{%0,%1,%2,%3}, {%4,%5,%6,%7}, {%8,%9}, {%0,%1,%2,%3};" \
        : "+f"((d)[0]), "+f"((d)[1]), "+f"((d)[2]), "+f"((d)[3]) \
        : "r"((a)[0]), "r"((a)[1]), "r"((a)[2]), "r"((a)[3]), "r"(b0), "r"(b1))
#define CP16(dst, src) \
    asm volatile("cp.async.cg.shared.global [%0], [%1], 16;" :: "r"(dst), "l"(src))
#define CP16Z(dst, src, sz) \
    asm volatile("cp.async.cg.shared.global [%0], [%1], 16, %2;" :: "r"(dst), "l"(src), "r"(sz))
#define CP_COMMIT() asm volatile("cp.async.commit_group;" ::: "memory")
#define CP_WAIT(n)  asm volatile("cp.async.wait_group %0;" :: "n"(n) : "memory")

// SMEM row = 256B data + 16B pad = 272B (odd 16B multiple -> conflict-free ldmatrix)
#define RS2 272
#define A_T (128*RS2)                 // 34816
#define W_T (64*RS2)                  // 17408
// gconv: A0 | A1 | W0 | W1 | red | idx  -> 2 CTAs/SM
#define G_A1   A_T
#define G_W0   (2*A_T)                // 69632
#define G_W1   (2*A_T + W_T)          // 87040
#define G_RED  (2*A_T + 2*W_T)        // 104448, 128 floats
#define G_IDX  (G_RED + 512)          // 104960
#define SMEM_G (G_IDX + 128*KK9*4)    // 109568
// wconv: A(132 rows) | W0 | W1 | red
#define AW_T   (132*RS2)              // 35904
#define W_W0   AW_T
#define W_W1   (AW_T + W_T)           // 53312
#define W_RED  (AW_T + 2*W_T)         // 70720
#define SMEM_W (W_RED + 512)          // 71232

// ---------------- compute: 8 k16-steps, single-pass fp16 mma (tile 128x64) ----------------
// B: two o-tiles merged per LDSM4 (lanes 16-31 read o-rows +8).
__device__ __forceinline__ void compute8(uint32_t aB, uint32_t wB,
    uint32_t aOff, uint32_t bOff, float acc[2][4][4])
{
#pragma unroll
    for (int kk = 0; kk < 8; kk++) {
        uint32_t ko = kk * 32;
        uint32_t ah[2][4], bf[2][4];
#pragma unroll
        for (int mt = 0; mt < 2; mt++)
            LDSM4(ah[mt], aB + aOff + mt*16*RS2 + ko);
#pragma unroll
        for (int op = 0; op < 2; op++)
            LDSM4(bf[op], wB + bOff + op*16*RS2 + ko);
#pragma unroll
        for (int mt = 0; mt < 2; mt++)
#pragma unroll
            for (int op = 0; op < 2; op++) {
                MMA_F16(acc[mt][op*2+0], ah[mt], bf[op][0], bf[op][1]);
                MMA_F16(acc[mt][op*2+1], ah[mt], bf[op][2], bf[op][3]);
            }
    }
}

// ---------------- epilogue: store raw out + fused BN stats (o-half aware) ----------------
__device__ __forceinline__ void epilogue(float acc[2][4][4], float* outb, float* red,
    int b, int n0, int oh, int nt, int wm, int wo, int lane, int tid)
{
#pragma unroll
    for (int ot = 0; ot < 4; ot++) {
        float s0 = 0.f, s1 = 0.f, q0 = 0.f, q1 = 0.f;
        int og = oh*64 + wo*32 + ot*8 + 2*(lane & 3);
#pragma unroll
        for (int mt = 0; mt < 2; mt++) {
            float c0 = acc[mt][ot][0], c1 = acc[mt][ot][1];
            float c2 = acc[mt][ot][2], c3 = acc[mt][ot][3];
            int n1 = n0 + wm*32 + mt*16 + (lane >> 2);
            float* o1 = outb + ((size_t)b*NNp + n1)*CC + og;
            *(float2*)o1          = make_float2(c0, c1);
            *(float2*)(o1 + 8*CC) = make_float2(c2, c3);
            s0 += c0 + c2;  s1 += c1 + c3;
            q0 += c0*c0 + c2*c2;  q1 += c1*c1 + c3*c3;
        }
#pragma unroll
        for (int m2 = 4; m2 <= 16; m2 <<= 1) {
            s0 += __shfl_xor_sync(0xffffffffu, s0, m2);
            s1 += __shfl_xor_sync(0xffffffffu, s1, m2);
            q0 += __shfl_xor_sync(0xffffffffu, q0, m2);
            q1 += __shfl_xor_sync(0xffffffffu, q1, m2);
        }
        if (lane < 4) {
            int o4 = wo*32 + ot*8 + 2*lane;
            atomicAdd(&red[o4],     s0);
            atomicAdd(&red[o4 + 1], s1);
            atomicAdd(&red[64 + o4],     q0);
            atomicAdd(&red[64 + o4 + 1], q1);
        }
    }
    __syncthreads();
    int row = b*256 + nt;
    if (tid < 128) {
        int isq = tid >> 6, ol = tid & 63;
        d_part[((size_t)(isq*128 + oh*64 + ol))*PROWS + row] = red[isq*64 + ol];
    }
}

// ---------------- gather conv: A+W fully double-buffered cp.async pipeline ----------------
__global__ __launch_bounds__(256, 2) void k_gconv(int plSel, const int* __restrict__ eidx, int wSel)
{
    extern __shared__ char smem[];
    float* red = (float*)(smem + G_RED);
    int* sidx = (int*)(smem + G_IDX);

    int tid = threadIdx.x, lane = tid & 31, wid = tid >> 5;
    int wm = wid & 3, wo = wid >> 2;                 // 4 x 2 warp grid
    int nt = blockIdx.x, oh = blockIdx.y, b = blockIdx.z;
    int n0 = nt * 128;

    const char* pl = (const char*)(plSel ? d_pl1 : d_pl0);
    const char* wsrc = (const char*)d_wg + (size_t)(wSel*KK9)*CC*256;

    if (tid < 128) red[tid] = 0.0f;
    for (int i = tid; i < 128*KK9; i += 256)
        sidx[i] = eidx[((size_t)b*NNp + n0)*KK9 + i];
    __syncthreads();

    float acc[2][4][4];
#pragma unroll
    for (int mt = 0; mt < 2; mt++)
#pragma unroll
        for (int ot = 0; ot < 4; ot++)
#pragma unroll
            for (int q = 0; q < 4; q++) acc[mt][ot][q] = 0.0f;

    uint32_t aOff = (uint32_t)(wm*32 + (lane & 15))*RS2 + (lane >> 4)*16;
    uint32_t bOff = (uint32_t)(wo*32 + (lane & 7) + ((lane >> 4)&1)*8)*RS2 + ((lane >> 3) & 1)*16;
    uint32_t smB = smem_u32(smem);

    // A: 2 rows per CP16 warp-instr (lanes 0-15 even row, 16-31 odd), 8 instrs/warp
#define STAGE_A(k_, bufOff_) do { \
        _Pragma("unroll") \
        for (int u_ = 0; u_ < 8; u_++) { \
            int rr_ = wid*16 + u_*2 + (lane >> 4); \
            const char* sa_ = pl + ((size_t)(b*NNp + sidx[rr_*KK9 + (k_)]))*256 + (lane & 15)*16; \
            CP16(smB + (bufOff_) + (uint32_t)rr_*RS2 + (lane & 15)*16, sa_); \
        } \
    } while (0)
    // W: 64 rows of this o-half, 4 instrs/warp
#define STAGE_W(k_, bufOff_) do { \
        _Pragma("unroll") \
        for (int u_ = 0; u_ < 4; u_++) { \
            int rr_ = wid*8 + u_*2 + (lane >> 4); \
            const char* sw_ = wsrc + ((size_t)((k_)*128 + oh*64 + rr_))*256 + (lane & 15)*16; \
            CP16(smB + (bufOff_) + (uint32_t)rr_*RS2 + (lane & 15)*16, sw_); \
        } \
    } while (0)

    STAGE_A(0, 0);    STAGE_W(0, G_W0); CP_COMMIT();
    STAGE_A(1, G_A1); STAGE_W(1, G_W1); CP_COMMIT();
    CP_WAIT(1);       // stage 0 complete
    __syncthreads();

    for (int k = 0; k < KK9; k++) {
        uint32_t aB = smB + ((k & 1) ? G_A1 : 0);
        uint32_t wB = smB + ((k & 1) ? G_W1 : G_W0);
        compute8(aB, wB, aOff, bOff, acc);
        __syncthreads();                       // all warps done with buf (k&1)
        if (k + 2 < KK9) {
            STAGE_A(k + 2, (k & 1) ? G_A1 : 0);
            STAGE_W(k + 2, (k & 1) ? G_W1 : G_W0);
            CP_COMMIT();
            CP_WAIT(1);                        // stage k+1 complete (issued 1 compute ago)
            __syncthreads();
        } else if (k + 1 < KK9) {
            CP_WAIT(0);
            __syncthreads();
        }
    }
#undef STAGE_A
#undef STAGE_W

    epilogue(acc, d_bufA, red, b, n0, oh, nt, wm, wo, lane, tid);
}

// ---------------- weighted conv: A staged once, W double-buffered, gw fp32 post-GEMM ----------------
__global__ __launch_bounds__(256, 2) void k_wconv(int plSel, int wSel)
{
    extern __shared__ char smem[];
    float* red = (float*)(smem + W_RED);

    int tid = threadIdx.x, lane = tid & 31, wid = tid >> 5;
    int wm = wid & 3, wo = wid >> 2;
    int nt = blockIdx.x, oh = blockIdx.y, b = blockIdx.z;
    int n0 = nt * 128;

    const char* pl = (const char*)(plSel ? d_pl1 : d_pl0);
    const char* wsrc = (const char*)d_wc + (size_t)(wSel*KS5)*CC*256;
    const float* gwp = d_gw + (size_t)b*KS5*NNp;

    if (tid < 128) red[tid] = 0.0f;

    float acc[2][4][4];
#pragma unroll
    for (int mt = 0; mt < 2; mt++)
#pragma unroll
        for (int ot = 0; ot < 4; ot++)
#pragma unroll
            for (int q = 0; q < 4; q++) acc[mt][ot][q] = 0.0f;

    uint32_t aOff = (uint32_t)(wm*32 + (lane & 15))*RS2 + (lane >> 4)*16;
    uint32_t bOff = (uint32_t)(wo*32 + (lane & 7) + ((lane >> 4)&1)*8)*RS2 + ((lane >> 3) & 1)*16;
    uint32_t smB = smem_u32(smem);

    // stage A once: 132 rows (n0-2 .. n0+129), zero-fill OOB; 2 rows per warp-instr
    for (int rr = wid*2 + (lane >> 4); rr < 132; rr += 16) {
        int m = n0 + rr - 2;
        bool v = (m >= 0) && (m < NNp);
        const char* sa = pl + ((size_t)(b*NNp + (v ? m : 0)))*256 + (lane & 15)*16;
        CP16Z(smB + (uint32_t)rr*RS2 + (lane & 15)*16, sa, v ? 16u : 0u);
    }
#define STAGE_WC(k_, bufOff_) do { \
        _Pragma("unroll") \
        for (int u_ = 0; u_ < 4; u_++) { \
            int rr_ = wid*8 + u_*2 + (lane >> 4); \
            const char* sw_ = wsrc + ((size_t)((k_)*128 + oh*64 + rr_))*256 + (lane & 15)*16; \
            CP16(smB + (bufOff_) + (uint32_t)rr_*RS2 + (lane & 15)*16, sw_); \
        } \
    } while (0)
    STAGE_WC(0, W_W0); CP_COMMIT();
    STAGE_WC(1, W_W1); CP_COMMIT();
    CP_WAIT(1);
    __syncthreads();

    int rowA = n0 + wm*32 + (lane >> 2);

    for (int k = 0; k < KS5; k++) {
        float P[2][4][4];
#pragma unroll
        for (int mt = 0; mt < 2; mt++)
#pragma unroll
            for (int ot = 0; ot < 4; ot++)
#pragma unroll
                for (int q = 0; q < 4; q++) P[mt][ot][q] = 0.0f;

        compute8(smB + (uint32_t)k*RS2, smB + ((k & 1) ? W_W1 : W_W0), aOff, bOff, P);

        // total += g[k, n] * P   (fp32, per accumulator row)
#pragma unroll
        for (int mt = 0; mt < 2; mt++) {
            float gA = gwp[(size_t)k*NNp + rowA + mt*16];
            float gB = gwp[(size_t)k*NNp + rowA + mt*16 + 8];
#pragma unroll
            for (int ot = 0; ot < 4; ot++) {
                acc[mt][ot][0] = fmaf(gA, P[mt][ot][0], acc[mt][ot][0]);
                acc[mt][ot][1] = fmaf(gA, P[mt][ot][1], acc[mt][ot][1]);
                acc[mt][ot][2] = fmaf(gB, P[mt][ot][2], acc[mt][ot][2]);
                acc[mt][ot][3] = fmaf(gB, P[mt][ot][3], acc[mt][ot][3]);
            }
        }
        __syncthreads();                       // all warps done with W buf (k&1)
        if (k + 2 < KS5) {
            STAGE_WC(k + 2, (k & 1) ? W_W1 : W_W0);
            CP_COMMIT();
            CP_WAIT(1);
            __syncthreads();
        } else if (k + 1 < KS5) {
            CP_WAIT(0);
            __syncthreads();
        }
    }
#undef STAGE_WC

    epilogue(acc, d_bufB, red, b, n0, oh, nt, wm, wo, lane, tid);
}

// ---------------- split x [B,C,N] -> fp16 plane [B,N,C] (transpose) ----------------
__global__ void k_splitX(const float* __restrict__ x, int dstSel) {
    __shared__ float tile[32][33];
    __half* dst = dstSel ? d_pl1 : d_pl0;
    int b = blockIdx.z, c0 = blockIdx.y*32, n0 = blockIdx.x*32;
    int tx = threadIdx.x, ty = threadIdx.y;
#pragma unroll
    for (int j = 0; j < 4; j++)
        tile[ty + 8*j][tx] = x[((size_t)b*CC + c0 + ty + 8*j)*NNp + n0 + tx];
    __syncthreads();
#pragma unroll
    for (int j = 0; j < 4; j++) {
        int nl = ty + 8*j;
        dst[((size_t)b*NNp + n0 + nl)*128 + c0 + tx] = __float2half_rn(tile[tx][nl]);
    }
}

// ---------------- split buffer [B,N,C] -> fp16 plane (BN+ReLU fold) ----------------
__global__ void k_split(int srcSel, int dstSel,
                        const float* __restrict__ gamma, const float* __restrict__ beta) {
    const float* src = srcSel ? d_bufB : d_bufA;
    __half* dst = dstSel ? d_pl1 : d_pl0;
    int t = threadIdx.x;
    size_t bn = (size_t)blockIdx.x*8 + (t >> 5);
    int c = (t & 31)*4;
    float4 v = *(const float4*)(src + bn*CC + c);
    float z[4] = {v.x, v.y, v.z, v.w};
#pragma unroll
    for (int e = 0; e < 4; e++) {
        float s = d_colsum[c + e], q = d_colsum[128 + c + e];
        float mean = s * (1.0f/MTOT);
        float var  = q * (1.0f/MTOT) - mean*mean;
        float sc = gamma[c + e] * rsqrtf(var + EPSb);
        float sh = beta[c + e] - mean*sc;
        z[e] = fmaxf(0.0f, sc*z[e] + sh);
    }
    __half2 h0 = __floats2half2_rn(z[0], z[1]);
    __half2 h1 = __floats2half2_rn(z[2], z[3]);
    *(uint2*)(dst + bn*128 + c) = make_uint2(*(uint32_t*)&h0, *(uint32_t*)&h1);
}

// ---------------- gaussian window weights ----------------
__global__ void k_gw(const float* __restrict__ co) {
    int b = blockIdx.y;
    int n = blockIdx.x*256 + threadIdx.x;
    float c0 = co[((size_t)b*3 + 0)*NNp + n];
    float c1 = co[((size_t)b*3 + 1)*NNp + n];
    float c2 = co[((size_t)b*3 + 2)*NNp + n];
#pragma unroll
    for (int k = 0; k < KS5; k++) {
        int m = n + k - 2;
        float g = 0.0f;
        if (m >= 0 && m < NNp) {
            float dx = co[((size_t)b*3 + 0)*NNp + m] - c0;
            float dy = co[((size_t)b*3 + 1)*NNp + m] - c1;
            float dz = co[((size_t)b*3 + 2)*NNp + m] - c2;
            g = expf(-0.5f * (dx*dx + dy*dy + dz*dz));
        }
        d_gw[((size_t)b*KS5 + k)*NNp + n] = g;
    }
}

// -------- weight prep: [o][c][k] fp32 -> [k][o][c] fp16 --------
__global__ void k_prepW(const float* __restrict__ w, int KK, int isC, int slot) {
    int i = blockIdx.x*256 + threadIdx.x;
    if (i >= KK*16384) return;
    int k = i >> 14;
    int rem = i & 16383;
    int o = rem >> 7, c = rem & 127;
    float v = w[((size_t)o*CC + c)*KK + k];
    __half* base = (isC ? d_wc : d_wg) + ((size_t)(slot*KK + k)*128 + o)*128;
    base[c] = __float2half_rn(v);
}

// ---------------- BN partial reduction ----------------
__global__ void k_red() {
    __shared__ float sh[256];
    int col = blockIdx.x, tid = threadIdx.x;
    const float* p = d_part + (size_t)col * PROWS;
    float s = 0.0f;
    for (int i = tid; i < PROWS; i += 256) s += p[i];
    sh[tid] = s;
    __syncthreads();
    for (int st = 128; st > 0; st >>= 1) {
        if (tid < st) sh[tid] += sh[tid + st];
        __syncthreads();
    }
    if (tid == 0) d_colsum[col] = sh[0];
}

// ---------------- final: out = relu(BN(bufB) + x), back to [B,C,N] ----------------
__global__ void k_final(const float* __restrict__ x,
                        const float* __restrict__ gamma,
                        const float* __restrict__ beta,
                        float* __restrict__ out)
{
    __shared__ float tile[32][33];
    __shared__ float sc[32], sh[32];
    int b = blockIdx.z, c0 = blockIdx.y*32, n0 = blockIdx.x*32;
    int tx = threadIdx.x, ty = threadIdx.y;
    if (ty == 0) {
        int c = c0 + tx;
        float s = d_colsum[c], q = d_colsum[128 + c];
        float mean = s * (1.0f/MTOT);
        float var  = q * (1.0f/MTOT) - mean*mean;
        float a = gamma[c] * rsqrtf(var + EPSb);
        sc[tx] = a;
        sh[tx] = beta[c] - mean*a;
    }
    __syncthreads();
#pragma unroll
    for (int j = 0; j < 4; j++) {
        int n = n0 + ty + 8*j;
        float v = d_bufB[((size_t)b*NNp + n)*CC + c0 + tx];
        tile[ty + 8*j][tx] = sc[tx]*v + sh[tx];
    }
    __syncthreads();
#pragma unroll
    for (int j = 0; j < 4; j++) {
        int c = c0 + ty + 8*j;
        size_t o = ((size_t)b*CC + c)*NNp + n0 + tx;
        out[o] = fmaxf(0.0f, tile[tx][ty + 8*j] + x[o]);
    }
}

// ---------------- launch ----------------
extern "C" void kernel_launch(void* const* d_in, const int* in_sizes, int n_in,
                              void* d_out, int out_size)
{
    const float* x    = (const float*)d_in[0];
    const int*   ei   = (const int*)d_in[1];
    const float* co   = (const float*)d_in[2];
    const float* w2d1 = (const float*)d_in[3];
    const float* g2d1 = (const float*)d_in[4];
    const float* b2d1 = (const float*)d_in[5];
    const float* wc1  = (const float*)d_in[6];
    const float* g1d1 = (const float*)d_in[7];
    const float* b1d1 = (const float*)d_in[8];
    const float* w2d2 = (const float*)d_in[9];
    const float* g2d2 = (const float*)d_in[10];
    const float* b2d2 = (const float*)d_in[11];
    const float* wc2  = (const float*)d_in[12];
    const float* g1d2 = (const float*)d_in[13];
    const float* b1d2 = (const float*)d_in[14];
    float* out = (float*)d_out;

    cudaFuncSetAttribute(k_gconv, cudaFuncAttributeMaxDynamicSharedMemorySize, SMEM_G);
    cudaFuncSetAttribute(k_wconv, cudaFuncAttributeMaxDynamicSharedMemorySize, SMEM_W);

    dim3 g(256, 2, BB);   // n-tile, o-half, batch -> 2048 CTAs, 2 per SM

    // first heavy GEMM at user-launch #4 (the ncu-captured slot)
    k_splitX<<<dim3(NNp/32, CC/32, BB), dim3(32, 8)>>>(x, 0);          // #1
    k_prepW<<<(KK9*16384 + 255)/256, 256>>>(w2d1, KK9, 0, 0);          // #2
    k_gw<<<dim3(NNp/256, BB), 256>>>(co);                              // #3

    // block 1
    k_gconv<<<g, 256, SMEM_G>>>(0, ei, 0);                             // #4  pl0 -> bufA
    k_red<<<256, 256>>>();
    k_split<<<BB*NNp/8, 256>>>(0, 1, g2d1, b2d1);                      // bufA -> pl1
    k_prepW<<<(KS5*16384 + 255)/256, 256>>>(wc1,  KS5, 1, 0);
    k_wconv<<<g, 256, SMEM_W>>>(1, 0);                                 // pl1 -> bufB
    k_red<<<256, 256>>>();
    k_split<<<BB*NNp/8, 256>>>(1, 0, g1d1, b1d1);                      // bufB -> pl0
    // block 2
    k_prepW<<<(KK9*16384 + 255)/256, 256>>>(w2d2, KK9, 0, 1);
    k_gconv<<<g, 256, SMEM_G>>>(0, ei, 1);                             // pl0 -> bufA
    k_red<<<256, 256>>>();
    k_split<<<BB*NNp/8, 256>>>(0, 1, g2d2, b2d2);                      // bufA -> pl1
    k_prepW<<<(KS5*16384 + 255)/256, 256>>>(wc2,  KS5, 1, 1);
    k_wconv<<<g, 256, SMEM_W>>>(1, 1);                                 // pl1 -> bufB
    k_red<<<256, 256>>>();
    // residual + relu + transpose back
    k_final<<<dim3(NNp/32, CC/32, BB), dim3(32, 8)>>>(x, g1d2, b1d2, out);
}